// round 3
// baseline (speedup 1.0000x reference)
#include <cuda_runtime.h>

#define DD 96
#define HH 320
#define WW 320
#define NVOX (DD*HH*WW)
#define CIN 64
#define COUT 64
#define EPSV 1e-5f
#define SLOPE 0.01f

// Dense coord->row+1 map (0 = empty). Zero-initialized at module load;
// each launch clears exactly the cells it touched so graph replays are clean.
__device__ int g_grid[NVOX];
__device__ float g_stats[2 * COUT];

__global__ void scatter_kernel(const int* __restrict__ coords, int n) {
    int i = blockIdx.x * blockDim.x + threadIdx.x;
    if (i < 2 * COUT) g_stats[i] = 0.0f;
    if (i >= n) return;
    int z = coords[3 * i + 0];
    int y = coords[3 * i + 1];
    int x = coords[3 * i + 2];
    g_grid[(z * HH + y) * WW + x] = i + 1;
}

__global__ void clear_kernel(const int* __restrict__ coords, int n) {
    int i = blockIdx.x * blockDim.x + threadIdx.x;
    if (i >= n) return;
    int z = coords[3 * i + 0];
    int y = coords[3 * i + 1];
    int x = coords[3 * i + 2];
    g_grid[(z * HH + y) * WW + x] = 0;
}

// ---------------------------------------------------------------------------
// Fused conv + stats. 64 rows per 256-thread block.
//   - center tap: SMEM-tiled GEMM (W13 + feature tile staged in SMEM)
//   - off-center taps: neighbor table in SMEM, accumulated into the same regs
//   - per-channel sum/sumsq reduced in-block, one atomicAdd per channel
// Thread mapping: rg = tid>>4 owns rows rg*4..rg*4+3; c4 = (tid&15)*4 cols.
// ---------------------------------------------------------------------------
#define BROWS 64
#define FSTR 68   // padded feature row stride (floats) to avoid bank conflicts

__global__ void __launch_bounds__(256) fused_conv_kernel(
    const float* __restrict__ feat, const int* __restrict__ coords,
    const float* __restrict__ wgt, float* __restrict__ out, int n)
{
    __shared__ float sW[CIN * COUT];       // 16 KB   W13 [ci][co]
    __shared__ float sF[BROWS * FSTR];     // 17.4 KB feature tile [r][ci]
    __shared__ int   snbr[BROWS][26];      // 6.7 KB  off-center neighbor rows
    __shared__ int   scoord[BROWS * 3];    // 768 B
    __shared__ float sstat[2 * COUT];      // 512 B

    const int tid   = threadIdx.x;
    const int rbase = blockIdx.x * BROWS;

    // ---- Stage: W13, feature tile, coords, zero stats ----
    {
        const float* w13 = wgt + (size_t)13 * CIN * COUT;
        #pragma unroll
        for (int t = 0; t < 4; t++) {
            int e = (tid + t * 256) * 4;
            *(float4*)&sW[e] = *(const float4*)&w13[e];
        }
        #pragma unroll
        for (int t = 0; t < 4; t++) {
            int e  = tid + t * 256;      // float4 index: 64 rows x 16
            int r  = e >> 4;
            int q  = e & 15;
            int gr = rbase + r;
            float4 v = (gr < n)
                ? *(const float4*)&feat[(size_t)gr * CIN + q * 4]
                : make_float4(0.f, 0.f, 0.f, 0.f);
            *(float4*)&sF[r * FSTR + q * 4] = v;
        }
        if (tid < BROWS * 3) {
            int gi = rbase * 3 + tid;
            scoord[tid] = (rbase + tid / 3 < n) ? coords[gi] : -1000;
        }
        if (tid < 2 * COUT) sstat[tid] = 0.0f;
    }
    __syncthreads();

    // ---- Neighbor lookups (26 off-center taps per row), issued BEFORE the
    //      GEMM so the random-access g_grid latency hides behind compute. ----
    for (int idx = tid; idx < BROWS * 26; idx += 256) {
        int v  = idx / 26;
        int kk = idx - v * 26;
        int k  = kk + (kk >= 13);        // skip center
        int val = 0;
        int z = scoord[3 * v + 0] + k / 9       - 1;
        int y = scoord[3 * v + 1] + (k / 3) % 3 - 1;
        int x = scoord[3 * v + 2] + k % 3       - 1;
        if (z >= 0 && z < DD && y >= 0 && y < HH && x >= 0 && x < WW)
            val = g_grid[(z * HH + y) * WW + x];
        snbr[v][kk] = val - 1;           // -1 => empty / OOB / past n
    }

    // ---- Center GEMM (4 rows x 4 cols per thread) ----
    const int rg = tid >> 4;
    const int c4 = (tid & 15) << 2;
    const int r0 = rg * 4;

    float4 acc[4];
    #pragma unroll
    for (int r = 0; r < 4; r++) acc[r] = make_float4(0.f, 0.f, 0.f, 0.f);

    #pragma unroll 8
    for (int ci = 0; ci < CIN; ci++) {
        float4 w = *(const float4*)&sW[ci * COUT + c4];
        #pragma unroll
        for (int r = 0; r < 4; r++) {
            float f = sF[(r0 + r) * FSTR + ci];
            acc[r].x += f * w.x; acc[r].y += f * w.y;
            acc[r].z += f * w.z; acc[r].w += f * w.w;
        }
    }

    __syncthreads();   // snbr complete

    // ---- Off-center taps: fixed (row, k) order => deterministic fp sums ----
    #pragma unroll
    for (int rl = 0; rl < 4; rl++) {
        const int v = r0 + rl;
        for (int kk = 0; kk < 26; kk++) {
            int j = snbr[v][kk];
            if (j < 0) continue;
            int ka = kk + (kk >= 13);
            const float* fb = feat + (size_t)j * CIN;
            const float* wb = wgt + (size_t)ka * CIN * COUT + c4;
            #pragma unroll 4
            for (int ci = 0; ci < CIN; ci += 4) {
                float4 f = *(const float4*)(fb + ci);
                float4 w;
                w = *(const float4*)(wb + (ci + 0) * COUT);
                acc[rl].x += f.x * w.x; acc[rl].y += f.x * w.y;
                acc[rl].z += f.x * w.z; acc[rl].w += f.x * w.w;
                w = *(const float4*)(wb + (ci + 1) * COUT);
                acc[rl].x += f.y * w.x; acc[rl].y += f.y * w.y;
                acc[rl].z += f.y * w.z; acc[rl].w += f.y * w.w;
                w = *(const float4*)(wb + (ci + 2) * COUT);
                acc[rl].x += f.z * w.x; acc[rl].y += f.z * w.y;
                acc[rl].z += f.z * w.z; acc[rl].w += f.z * w.w;
                w = *(const float4*)(wb + (ci + 3) * COUT);
                acc[rl].x += f.w * w.x; acc[rl].y += f.w * w.y;
                acc[rl].z += f.w * w.z; acc[rl].w += f.w * w.w;
            }
        }
    }

    // ---- Write outputs ----
    #pragma unroll
    for (int rl = 0; rl < 4; rl++) {
        int gr = rbase + r0 + rl;
        if (gr < n)
            *(float4*)&out[(size_t)gr * COUT + c4] = acc[rl];
    }

    // ---- In-block BN stats (rows >= n contribute exact zeros) ----
    {
        float sx = acc[0].x + acc[1].x + acc[2].x + acc[3].x;
        float sy = acc[0].y + acc[1].y + acc[2].y + acc[3].y;
        float sz = acc[0].z + acc[1].z + acc[2].z + acc[3].z;
        float sw = acc[0].w + acc[1].w + acc[2].w + acc[3].w;
        float qx = acc[0].x*acc[0].x + acc[1].x*acc[1].x
                 + acc[2].x*acc[2].x + acc[3].x*acc[3].x;
        float qy = acc[0].y*acc[0].y + acc[1].y*acc[1].y
                 + acc[2].y*acc[2].y + acc[3].y*acc[3].y;
        float qz = acc[0].z*acc[0].z + acc[1].z*acc[1].z
                 + acc[2].z*acc[2].z + acc[3].z*acc[3].z;
        float qw = acc[0].w*acc[0].w + acc[1].w*acc[1].w
                 + acc[2].w*acc[2].w + acc[3].w*acc[3].w;
        atomicAdd(&sstat[c4 + 0], sx);
        atomicAdd(&sstat[c4 + 1], sy);
        atomicAdd(&sstat[c4 + 2], sz);
        atomicAdd(&sstat[c4 + 3], sw);
        atomicAdd(&sstat[COUT + c4 + 0], qx);
        atomicAdd(&sstat[COUT + c4 + 1], qy);
        atomicAdd(&sstat[COUT + c4 + 2], qz);
        atomicAdd(&sstat[COUT + c4 + 3], qw);
    }
    __syncthreads();
    if (tid < 2 * COUT)
        atomicAdd(&g_stats[tid], sstat[tid]);
}

__global__ void __launch_bounds__(256) bn_kernel(
    float4* __restrict__ out, const float* __restrict__ gamma,
    const float* __restrict__ beta, int n4, float invN)
{
    __shared__ float ssc[COUT], sbi[COUT];
    if (threadIdx.x < COUT) {
        float mean = g_stats[threadIdx.x] * invN;
        float var  = g_stats[COUT + threadIdx.x] * invN - mean * mean;
        float sc   = gamma[threadIdx.x] * rsqrtf(var + EPSV);
        ssc[threadIdx.x] = sc;
        sbi[threadIdx.x] = beta[threadIdx.x] - mean * sc;
    }
    __syncthreads();

    int idx = blockIdx.x * blockDim.x + threadIdx.x;
    if (idx >= n4) return;
    int c4 = (idx & 15) << 2;

    float4 vv = out[idx];
    float r;
    r = vv.x * ssc[c4 + 0] + sbi[c4 + 0]; vv.x = (r >= 0.f) ? r : SLOPE * r;
    r = vv.y * ssc[c4 + 1] + sbi[c4 + 1]; vv.y = (r >= 0.f) ? r : SLOPE * r;
    r = vv.z * ssc[c4 + 2] + sbi[c4 + 2]; vv.z = (r >= 0.f) ? r : SLOPE * r;
    r = vv.w * ssc[c4 + 3] + sbi[c4 + 3]; vv.w = (r >= 0.f) ? r : SLOPE * r;
    out[idx] = vv;
}

extern "C" void kernel_launch(void* const* d_in, const int* in_sizes, int n_in,
                              void* d_out, int out_size)
{
    const float* feat   = (const float*)d_in[0];
    const int*   coords = (const int*)  d_in[1];
    const float* wgt    = (const float*)d_in[2];
    const float* gamma  = (const float*)d_in[3];
    const float* beta   = (const float*)d_in[4];
    float*       out    = (float*)d_out;

    const int n = in_sizes[0] / CIN;

    scatter_kernel<<<(n + 255) / 256, 256>>>(coords, n);
    fused_conv_kernel<<<(n + BROWS - 1) / BROWS, 256>>>(feat, coords, wgt, out, n);
    bn_kernel<<<(n * (COUT / 4) + 255) / 256, 256>>>(
        (float4*)out, gamma, beta, n * (COUT / 4), 1.0f / (float)n);
    clear_kernel<<<(n + 255) / 256, 256>>>(coords, n);
}

// round 4
// speedup vs baseline: 1.0953x; 1.0953x over previous
#include <cuda_runtime.h>

#define DD 96
#define HH 320
#define WW 320
#define NVOX (DD*HH*WW)
#define CIN 64
#define COUT 64
#define EPSV 1e-5f
#define SLOPE 0.01f

__device__ int g_grid[NVOX];        // coord -> row+1, 0 = empty
__device__ float g_stats[2 * COUT]; // per-channel sum / sumsq

__global__ void scatter_kernel(const int* __restrict__ coords, int n) {
    int i = blockIdx.x * blockDim.x + threadIdx.x;
    if (i < 2 * COUT) g_stats[i] = 0.0f;
    if (i >= n) return;
    int z = coords[3 * i + 0];
    int y = coords[3 * i + 1];
    int x = coords[3 * i + 2];
    g_grid[(z * HH + y) * WW + x] = i + 1;
}

__global__ void clear_kernel(const int* __restrict__ coords, int n) {
    int i = blockIdx.x * blockDim.x + threadIdx.x;
    if (i >= n) return;
    int z = coords[3 * i + 0];
    int y = coords[3 * i + 1];
    int x = coords[3 * i + 2];
    g_grid[(z * HH + y) * WW + x] = 0;
}

// ---------------------------------------------------------------------------
// Center tap (k=13, always valid): dense GEMM out = feat @ W13.
// 128 rows x 64 cols per 256-thread block; 8 rows x 4 cols per thread.
// ---------------------------------------------------------------------------
#define GROWS 128
#define FSTRIDE 68

__global__ void __launch_bounds__(256) center_gemm_kernel(
    const float* __restrict__ feat, const float* __restrict__ wgt,
    float* __restrict__ out, int n)
{
    __shared__ float sW[CIN * COUT];
    __shared__ float sF[GROWS * FSTRIDE];

    const int tid   = threadIdx.x;
    const int rbase = blockIdx.x * GROWS;
    const float* w13 = wgt + (size_t)13 * CIN * COUT;

    #pragma unroll
    for (int t = 0; t < 4; t++) {
        int e = (tid + t * 256) * 4;
        *(float4*)&sW[e] = *(const float4*)&w13[e];
    }
    #pragma unroll
    for (int t = 0; t < 8; t++) {
        int e  = tid + t * 256;
        int r  = e >> 4;
        int q  = e & 15;
        int gr = rbase + r;
        float4 v = (gr < n) ? *(const float4*)&feat[(size_t)gr * CIN + q * 4]
                            : make_float4(0.f, 0.f, 0.f, 0.f);
        *(float4*)&sF[r * FSTRIDE + q * 4] = v;
    }
    __syncthreads();

    const int c4 = (tid & 15) << 2;
    const int r0 = (tid >> 4) * 8;

    float4 acc[8];
    #pragma unroll
    for (int r = 0; r < 8; r++) acc[r] = make_float4(0.f, 0.f, 0.f, 0.f);

    #pragma unroll 8
    for (int ci = 0; ci < CIN; ci++) {
        float4 w = *(const float4*)&sW[ci * COUT + c4];
        #pragma unroll
        for (int r = 0; r < 8; r++) {
            float f = sF[(r0 + r) * FSTRIDE + ci];
            acc[r].x += f * w.x; acc[r].y += f * w.y;
            acc[r].z += f * w.z; acc[r].w += f * w.w;
        }
    }

    #pragma unroll
    for (int r = 0; r < 8; r++) {
        int gr = rbase + r0 + r;
        if (gr < n)
            *(float4*)&out[(size_t)gr * COUT + c4] = acc[r];
    }
}

// ---------------------------------------------------------------------------
// Remainder + BN stats. 16 voxels per 256-thread block, 16 threads/voxel
// owning 4 channels. Warp-uniform tap skip across the two voxel groups in a
// warp. Final out value (center + taps) produced in registers -> BN stats
// reduced in-block (shfl + smem) -> 128 global atomicAdds per block.
// ---------------------------------------------------------------------------
#define VPB 16

__global__ void __launch_bounds__(256) remainder_stats_kernel(
    const float* __restrict__ feat, const int* __restrict__ coords,
    const float* __restrict__ wgt, float* __restrict__ out, int n)
{
    __shared__ float sfeat[VPB][CIN];       // 4 KB
    __shared__ int   snbr[VPB][26];         // 1.7 KB
    __shared__ int   scoord[VPB * 3];
    __shared__ float wred[2][8][COUT];      // 4 KB per-warp partial sums

    const int tid   = threadIdx.x;
    const int vbase = blockIdx.x * VPB;

    if (tid < VPB * 3)
        scoord[tid] = (vbase + tid / 3 < n) ? coords[vbase * 3 + tid] : -1000;
    __syncthreads();

    for (int idx = tid; idx < VPB * 26; idx += 256) {
        int v  = idx / 26;
        int kk = idx - v * 26;
        int k  = kk + (kk >= 13);
        int val = 0;
        int z = scoord[3 * v + 0] + k / 9       - 1;
        int y = scoord[3 * v + 1] + (k / 3) % 3 - 1;
        int x = scoord[3 * v + 2] + k % 3       - 1;
        if (z >= 0 && z < DD && y >= 0 && y < HH && x >= 0 && x < WW)
            val = g_grid[(z * HH + y) * WW + x];
        snbr[v][kk] = val - 1;
    }
    __syncthreads();

    const int v  = tid >> 4;
    const int c4 = (tid & 15) << 2;
    const int i  = vbase + v;

    float4 acc = make_float4(0.f, 0.f, 0.f, 0.f);
    bool used = false;

    for (int kk = 0; kk < 26; kk++) {
        int jme = snbr[v][kk];
        int jot = snbr[v ^ 1][kk];
        if (jme < 0 && jot < 0) continue;   // warp-uniform skip

        if (jme >= 0)
            *(float4*)&sfeat[v][c4] =
                *(const float4*)&feat[(size_t)jme * CIN + c4];
        __syncwarp();

        if (jme >= 0) {
            used = true;
            int ka = kk + (kk >= 13);
            const float* wb = wgt + (size_t)ka * CIN * COUT + c4;
            #pragma unroll
            for (int ci = 0; ci < CIN; ci += 4) {
                float4 s = *(const float4*)&sfeat[v][ci];
                float4 w;
                w = *(const float4*)(wb + (ci + 0) * COUT);
                acc.x += s.x * w.x; acc.y += s.x * w.y;
                acc.z += s.x * w.z; acc.w += s.x * w.w;
                w = *(const float4*)(wb + (ci + 1) * COUT);
                acc.x += s.y * w.x; acc.y += s.y * w.y;
                acc.z += s.y * w.z; acc.w += s.y * w.w;
                w = *(const float4*)(wb + (ci + 2) * COUT);
                acc.x += s.z * w.x; acc.y += s.z * w.y;
                acc.z += s.z * w.z; acc.w += s.z * w.w;
                w = *(const float4*)(wb + (ci + 3) * COUT);
                acc.x += s.w * w.x; acc.y += s.w * w.y;
                acc.z += s.w * w.z; acc.w += s.w * w.w;
            }
        }
        __syncwarp();
    }

    // Final value for this (row, 4 channels); zero for padded rows.
    float4 o = make_float4(0.f, 0.f, 0.f, 0.f);
    if (i < n) {
        o = *(float4*)&out[(size_t)i * COUT + c4];
        if (used) {
            o.x += acc.x; o.y += acc.y; o.z += acc.z; o.w += acc.w;
            *(float4*)&out[(size_t)i * COUT + c4] = o;
        }
    }

    // BN stats: reduce across the two voxel groups in this warp (lanes l,l^16
    // hold the same channels), then across the 8 warps via smem.
    float4 q = make_float4(o.x * o.x, o.y * o.y, o.z * o.z, o.w * o.w);
    o.x += __shfl_xor_sync(0xffffffffu, o.x, 16);
    o.y += __shfl_xor_sync(0xffffffffu, o.y, 16);
    o.z += __shfl_xor_sync(0xffffffffu, o.z, 16);
    o.w += __shfl_xor_sync(0xffffffffu, o.w, 16);
    q.x += __shfl_xor_sync(0xffffffffu, q.x, 16);
    q.y += __shfl_xor_sync(0xffffffffu, q.y, 16);
    q.z += __shfl_xor_sync(0xffffffffu, q.z, 16);
    q.w += __shfl_xor_sync(0xffffffffu, q.w, 16);

    const int w = tid >> 5;
    if ((tid & 31) < 16) {
        *(float4*)&wred[0][w][c4] = o;
        *(float4*)&wred[1][w][c4] = q;
    }
    __syncthreads();

    if (tid < 2 * COUT) {
        int half = tid >> 6;
        int c    = tid & 63;
        float s = 0.f;
        #pragma unroll
        for (int ww = 0; ww < 8; ww++) s += wred[half][ww][c];
        atomicAdd(&g_stats[tid], s);
    }
}

__global__ void __launch_bounds__(256) bn_kernel(
    float4* __restrict__ out, const float* __restrict__ gamma,
    const float* __restrict__ beta, int n4, float invN)
{
    __shared__ float ssc[COUT], sbi[COUT];
    if (threadIdx.x < COUT) {
        float mean = g_stats[threadIdx.x] * invN;
        float var  = g_stats[COUT + threadIdx.x] * invN - mean * mean;
        float sc   = gamma[threadIdx.x] * rsqrtf(var + EPSV);
        ssc[threadIdx.x] = sc;
        sbi[threadIdx.x] = beta[threadIdx.x] - mean * sc;
    }
    __syncthreads();

    int idx = blockIdx.x * blockDim.x + threadIdx.x;
    if (idx >= n4) return;
    int c4 = (idx & 15) << 2;

    float4 vv = out[idx];
    float r;
    r = vv.x * ssc[c4 + 0] + sbi[c4 + 0]; vv.x = (r >= 0.f) ? r : SLOPE * r;
    r = vv.y * ssc[c4 + 1] + sbi[c4 + 1]; vv.y = (r >= 0.f) ? r : SLOPE * r;
    r = vv.z * ssc[c4 + 2] + sbi[c4 + 2]; vv.z = (r >= 0.f) ? r : SLOPE * r;
    r = vv.w * ssc[c4 + 3] + sbi[c4 + 3]; vv.w = (r >= 0.f) ? r : SLOPE * r;
    out[idx] = vv;
}

extern "C" void kernel_launch(void* const* d_in, const int* in_sizes, int n_in,
                              void* d_out, int out_size)
{
    const float* feat   = (const float*)d_in[0];
    const int*   coords = (const int*)  d_in[1];
    const float* wgt    = (const float*)d_in[2];
    const float* gamma  = (const float*)d_in[3];
    const float* beta   = (const float*)d_in[4];
    float*       out    = (float*)d_out;

    const int n = in_sizes[0] / CIN;

    scatter_kernel<<<(n + 255) / 256, 256>>>(coords, n);
    center_gemm_kernel<<<(n + GROWS - 1) / GROWS, 256>>>(feat, wgt, out, n);
    remainder_stats_kernel<<<(n + VPB - 1) / VPB, 256>>>(feat, coords, wgt, out, n);
    bn_kernel<<<(n * (COUT / 4) + 255) / 256, 256>>>(
        (float4*)out, gamma, beta, n * (COUT / 4), 1.0f / (float)n);
    clear_kernel<<<(n + 255) / 256, 256>>>(coords, n);
}

// round 5
// speedup vs baseline: 1.6753x; 1.5296x over previous
#include <cuda_runtime.h>

#define DD 96
#define HH 320
#define WW 320
#define NVOX (DD*HH*WW)
#define CIN 64
#define COUT 64
#define EPSV 1e-5f
#define SLOPE 0.01f
#define RSLOTS 4096   // per-tap rulebook capacity (expected ~2250, sigma ~47)

__device__ int   g_grid[NVOX];          // coord -> row+1, 0 = empty
__device__ float g_stats[2 * COUT];     // per-channel sum / sumsq
__device__ int   g_cnt[27];             // per-tap pair counts
__device__ int2  g_rule[27][RSLOTS];    // (out_row, in_row) pairs per tap

__global__ void scatter_kernel(const int* __restrict__ coords, int n) {
    int i = blockIdx.x * blockDim.x + threadIdx.x;
    if (i < 2 * COUT) g_stats[i] = 0.0f;
    if (i < 27) g_cnt[i] = 0;
    if (i >= n) return;
    int z = coords[3 * i + 0];
    int y = coords[3 * i + 1];
    int x = coords[3 * i + 2];
    g_grid[(z * HH + y) * WW + x] = i + 1;
}

__global__ void clear_kernel(const int* __restrict__ coords, int n) {
    int i = blockIdx.x * blockDim.x + threadIdx.x;
    if (i >= n) return;
    int z = coords[3 * i + 0];
    int y = coords[3 * i + 1];
    int x = coords[3 * i + 2];
    g_grid[(z * HH + y) * WW + x] = 0;
}

// ---------------------------------------------------------------------------
// Rulebook build: probe 13 of the 26 off-center offsets, emit both directions.
// Pair (i, j) at tap k  =>  out[i] += feat[j] @ W[k]  and  out[j] += feat[i] @ W[26-k].
// ---------------------------------------------------------------------------
__global__ void __launch_bounds__(256) rulebook_kernel(
    const int* __restrict__ coords, int n)
{
    int t = blockIdx.x * blockDim.x + threadIdx.x;
    if (t >= n * 13) return;
    int v = t / 13;
    int k = t - v * 13;          // taps 0..12 (center is 13)

    int z = coords[3 * v + 0] + k / 9       - 1;
    int y = coords[3 * v + 1] + (k / 3) % 3 - 1;
    int x = coords[3 * v + 2] + k % 3       - 1;
    if (z < 0 || z >= DD || y < 0 || y >= HH || x < 0 || x >= WW) return;
    int val = g_grid[(z * HH + y) * WW + x];
    if (val == 0) return;
    int j = val - 1;

    int p0 = atomicAdd(&g_cnt[k], 1);
    if (p0 < RSLOTS) g_rule[k][p0] = make_int2(v, j);
    int p1 = atomicAdd(&g_cnt[26 - k], 1);
    if (p1 < RSLOTS) g_rule[26 - k][p1] = make_int2(j, v);
}

// ---------------------------------------------------------------------------
// Center tap (always valid): dense GEMM out = feat @ W13.
// 128 rows x 64 cols per 256-thread block; 8 rows x 4 cols per thread.
// ---------------------------------------------------------------------------
#define GROWS 128
#define FSTRIDE 68

__global__ void __launch_bounds__(256) center_gemm_kernel(
    const float* __restrict__ feat, const float* __restrict__ wgt,
    float* __restrict__ out, int n)
{
    __shared__ float sW[CIN * COUT];
    __shared__ float sF[GROWS * FSTRIDE];

    const int tid   = threadIdx.x;
    const int rbase = blockIdx.x * GROWS;
    const float* w13 = wgt + (size_t)13 * CIN * COUT;

    #pragma unroll
    for (int t = 0; t < 4; t++) {
        int e = (tid + t * 256) * 4;
        *(float4*)&sW[e] = *(const float4*)&w13[e];
    }
    #pragma unroll
    for (int t = 0; t < 8; t++) {
        int e  = tid + t * 256;
        int r  = e >> 4;
        int q  = e & 15;
        int gr = rbase + r;
        float4 v = (gr < n) ? *(const float4*)&feat[(size_t)gr * CIN + q * 4]
                            : make_float4(0.f, 0.f, 0.f, 0.f);
        *(float4*)&sF[r * FSTRIDE + q * 4] = v;
    }
    __syncthreads();

    const int c4 = (tid & 15) << 2;
    const int r0 = (tid >> 4) * 8;

    float4 acc[8];
    #pragma unroll
    for (int r = 0; r < 8; r++) acc[r] = make_float4(0.f, 0.f, 0.f, 0.f);

    #pragma unroll 8
    for (int ci = 0; ci < CIN; ci++) {
        float4 w = *(const float4*)&sW[ci * COUT + c4];
        #pragma unroll
        for (int r = 0; r < 8; r++) {
            float f = sF[(r0 + r) * FSTRIDE + ci];
            acc[r].x += f * w.x; acc[r].y += f * w.y;
            acc[r].z += f * w.z; acc[r].w += f * w.w;
        }
    }

    #pragma unroll
    for (int r = 0; r < 8; r++) {
        int gr = rbase + r0 + r;
        if (gr < n)
            *(float4*)&out[(size_t)gr * COUT + c4] = acc[r];
    }
}

// ---------------------------------------------------------------------------
// Tap GEMM: block = 64 rulebook pairs of ONE tap. W[k] staged once in SMEM,
// 64 gathered feature rows, 64x64x64 GEMM, scatter via atomicAdd.
// ---------------------------------------------------------------------------
__global__ void __launch_bounds__(256) tap_gemm_kernel(
    const float* __restrict__ feat, const float* __restrict__ wgt,
    float* __restrict__ out)
{
    const int ky = blockIdx.y;
    int cnt = g_cnt[ky];
    if (cnt > RSLOTS) cnt = RSLOTS;
    const int base = blockIdx.x * 64;
    if (base >= cnt) return;

    __shared__ float sW[CIN * COUT];     // 16 KB
    __shared__ float sF[64 * FSTRIDE];   // 17 KB
    __shared__ int2  sp[64];

    const int tid = threadIdx.x;

    {
        const float* wk = wgt + (size_t)ky * CIN * COUT;
        #pragma unroll
        for (int t = 0; t < 4; t++) {
            int e = (tid + t * 256) * 4;
            *(float4*)&sW[e] = *(const float4*)&wk[e];
        }
    }
    if (tid < 64)
        sp[tid] = (base + tid < cnt) ? g_rule[ky][base + tid]
                                     : make_int2(-1, -1);
    __syncthreads();

    #pragma unroll
    for (int t = 0; t < 4; t++) {
        int e = tid + t * 256;       // 64 rows x 16 float4
        int r = e >> 4;
        int q = e & 15;
        int j = sp[r].y;
        float4 v = (j >= 0) ? *(const float4*)&feat[(size_t)j * CIN + q * 4]
                            : make_float4(0.f, 0.f, 0.f, 0.f);
        *(float4*)&sF[r * FSTRIDE + q * 4] = v;
    }
    __syncthreads();

    const int c4 = (tid & 15) << 2;
    const int r0 = (tid >> 4) * 4;

    float4 acc[4];
    #pragma unroll
    for (int r = 0; r < 4; r++) acc[r] = make_float4(0.f, 0.f, 0.f, 0.f);

    #pragma unroll 8
    for (int ci = 0; ci < CIN; ci++) {
        float4 w = *(const float4*)&sW[ci * COUT + c4];
        #pragma unroll
        for (int r = 0; r < 4; r++) {
            float f = sF[(r0 + r) * FSTRIDE + ci];
            acc[r].x += f * w.x; acc[r].y += f * w.y;
            acc[r].z += f * w.z; acc[r].w += f * w.w;
        }
    }

    #pragma unroll
    for (int r = 0; r < 4; r++) {
        int i = sp[r0 + r].x;
        if (i >= 0) {
            float* ob = out + (size_t)i * COUT + c4;
            atomicAdd(ob + 0, acc[r].x);
            atomicAdd(ob + 1, acc[r].y);
            atomicAdd(ob + 2, acc[r].z);
            atomicAdd(ob + 3, acc[r].w);
        }
    }
}

// ---------------------------------------------------------------------------
// BN stats: coalesced float4 grid-stride read of out, shfl+smem reduce,
// 128 global atomicAdds per block.
// ---------------------------------------------------------------------------
__global__ void __launch_bounds__(256) reduce_kernel(
    const float* __restrict__ out, int n)
{
    const int tid = threadIdx.x;
    const int c4  = (tid & 15) << 2;
    const int rg  = tid >> 4;          // 16 rows per block per iteration

    float4 s = make_float4(0.f, 0.f, 0.f, 0.f);
    float4 q = make_float4(0.f, 0.f, 0.f, 0.f);

    for (int row = blockIdx.x * 16 + rg; row < n; row += gridDim.x * 16) {
        float4 v = *(const float4*)&out[(size_t)row * COUT + c4];
        s.x += v.x; s.y += v.y; s.z += v.z; s.w += v.w;
        q.x += v.x * v.x; q.y += v.y * v.y;
        q.z += v.z * v.z; q.w += v.w * v.w;
    }

    // lanes l and l^16 hold the same channels
    s.x += __shfl_xor_sync(0xffffffffu, s.x, 16);
    s.y += __shfl_xor_sync(0xffffffffu, s.y, 16);
    s.z += __shfl_xor_sync(0xffffffffu, s.z, 16);
    s.w += __shfl_xor_sync(0xffffffffu, s.w, 16);
    q.x += __shfl_xor_sync(0xffffffffu, q.x, 16);
    q.y += __shfl_xor_sync(0xffffffffu, q.y, 16);
    q.z += __shfl_xor_sync(0xffffffffu, q.z, 16);
    q.w += __shfl_xor_sync(0xffffffffu, q.w, 16);

    __shared__ float wred[2][8][COUT];
    const int w = tid >> 5;
    if ((tid & 31) < 16) {
        *(float4*)&wred[0][w][c4] = s;
        *(float4*)&wred[1][w][c4] = q;
    }
    __syncthreads();

    if (tid < 2 * COUT) {
        int half = tid >> 6;
        int c    = tid & 63;
        float acc = 0.f;
        #pragma unroll
        for (int ww = 0; ww < 8; ww++) acc += wred[half][ww][c];
        atomicAdd(&g_stats[tid], acc);
    }
}

__global__ void __launch_bounds__(256) bn_kernel(
    float4* __restrict__ out, const float* __restrict__ gamma,
    const float* __restrict__ beta, int n4, float invN)
{
    __shared__ float ssc[COUT], sbi[COUT];
    if (threadIdx.x < COUT) {
        float mean = g_stats[threadIdx.x] * invN;
        float var  = g_stats[COUT + threadIdx.x] * invN - mean * mean;
        float sc   = gamma[threadIdx.x] * rsqrtf(var + EPSV);
        ssc[threadIdx.x] = sc;
        sbi[threadIdx.x] = beta[threadIdx.x] - mean * sc;
    }
    __syncthreads();

    int idx = blockIdx.x * blockDim.x + threadIdx.x;
    if (idx >= n4) return;
    int c4 = (idx & 15) << 2;

    float4 vv = out[idx];
    float r;
    r = vv.x * ssc[c4 + 0] + sbi[c4 + 0]; vv.x = (r >= 0.f) ? r : SLOPE * r;
    r = vv.y * ssc[c4 + 1] + sbi[c4 + 1]; vv.y = (r >= 0.f) ? r : SLOPE * r;
    r = vv.z * ssc[c4 + 2] + sbi[c4 + 2]; vv.z = (r >= 0.f) ? r : SLOPE * r;
    r = vv.w * ssc[c4 + 3] + sbi[c4 + 3]; vv.w = (r >= 0.f) ? r : SLOPE * r;
    out[idx] = vv;
}

extern "C" void kernel_launch(void* const* d_in, const int* in_sizes, int n_in,
                              void* d_out, int out_size)
{
    const float* feat   = (const float*)d_in[0];
    const int*   coords = (const int*)  d_in[1];
    const float* wgt    = (const float*)d_in[2];
    const float* gamma  = (const float*)d_in[3];
    const float* beta   = (const float*)d_in[4];
    float*       out    = (float*)d_out;

    const int n = in_sizes[0] / CIN;

    scatter_kernel<<<(n + 255) / 256, 256>>>(coords, n);
    rulebook_kernel<<<(n * 13 + 255) / 256, 256>>>(coords, n);
    center_gemm_kernel<<<(n + GROWS - 1) / GROWS, 256>>>(feat, wgt, out, n);
    {
        dim3 grid(RSLOTS / 64, 27);
        tap_gemm_kernel<<<grid, 256>>>(feat, wgt, out);
    }
    reduce_kernel<<<592, 256>>>(out, n);
    bn_kernel<<<(n * (COUT / 4) + 255) / 256, 256>>>(
        (float4*)out, gamma, beta, n * (COUT / 4), 1.0f / (float)n);
    clear_kernel<<<(n + 255) / 256, 256>>>(coords, n);
}

// round 6
// speedup vs baseline: 1.6758x; 1.0003x over previous
#include <cuda_runtime.h>

typedef unsigned long long ull;

#define DD 96
#define HH 320
#define WW 320
#define NVOX (DD*HH*WW)
#define CIN 64
#define COUT 64
#define EPSV 1e-5f
#define SLOPE 0.01f
#define RSLOTS 4096   // per-tap rulebook capacity (expected ~2250)

__device__ int   g_grid[NVOX];          // coord -> row+1, 0 = empty
__device__ float g_stats[2 * COUT];     // per-channel sum / sumsq
__device__ int   g_cnt[27];             // per-tap pair counts
__device__ int2  g_rule[27][RSLOTS];    // (out_row, in_row) pairs per tap

__device__ __forceinline__ void ffma2(ull& acc, ull a, ull b) {
    asm("fma.rn.f32x2 %0, %1, %2, %0;" : "+l"(acc) : "l"(a), "l"(b));
}
__device__ __forceinline__ float fold(ull v) {
    return __uint_as_float((unsigned)v) + __uint_as_float((unsigned)(v >> 32));
}

__global__ void scatter_kernel(const int* __restrict__ coords, int n) {
    int i = blockIdx.x * blockDim.x + threadIdx.x;
    if (i < 2 * COUT) g_stats[i] = 0.0f;
    if (i < 27) g_cnt[i] = 0;
    if (i >= n) return;
    int z = coords[3 * i + 0];
    int y = coords[3 * i + 1];
    int x = coords[3 * i + 2];
    g_grid[(z * HH + y) * WW + x] = i + 1;
}

// Probe 13 of 26 off-center offsets; emit both directions.
__global__ void __launch_bounds__(256) rulebook_kernel(
    const int* __restrict__ coords, int n)
{
    int t = blockIdx.x * blockDim.x + threadIdx.x;
    if (t >= n * 13) return;
    int v = t / 13;
    int k = t - v * 13;

    int z = coords[3 * v + 0] + k / 9       - 1;
    int y = coords[3 * v + 1] + (k / 3) % 3 - 1;
    int x = coords[3 * v + 2] + k % 3       - 1;
    if (z < 0 || z >= DD || y < 0 || y >= HH || x < 0 || x >= WW) return;
    int val = g_grid[(z * HH + y) * WW + x];
    if (val == 0) return;
    int j = val - 1;

    int p0 = atomicAdd(&g_cnt[k], 1);
    if (p0 < RSLOTS) g_rule[k][p0] = make_int2(v, j);
    int p1 = atomicAdd(&g_cnt[26 - k], 1);
    if (p1 < RSLOTS) g_rule[26 - k][p1] = make_int2(j, v);
}

// ---------------------------------------------------------------------------
// Center tap: dense GEMM out = feat @ W13 using packed f32x2 FMA.
// 112 rows x 64 cols per 256-thread block; 7 rows x 4 strided cols/thread.
// Weights staged interleaved: sW2[p*128 + c*2 + h] = W[2p+h][c].
// Accumulator = (even-ci partial, odd-ci partial), folded at the end.
// ---------------------------------------------------------------------------
#define GROWS 112

__global__ void __launch_bounds__(256) center_gemm_kernel(
    const float* __restrict__ feat, const float* __restrict__ wgt,
    float* __restrict__ out, int n)
{
    __shared__ __align__(16) float sW2[CIN * COUT];    // 16 KB interleaved
    __shared__ __align__(16) float sF[GROWS * CIN];    // 28 KB [r][ci]

    const int tid   = threadIdx.x;
    const int rbase = blockIdx.x * GROWS;
    const float* w13 = wgt + 13 * CIN * COUT;

    #pragma unroll
    for (int t = 0; t < 4; t++) {
        int e  = tid + t * 256;           // 1024 float4 of W13
        int ci = e >> 4;
        int c0 = (e & 15) * 4;
        float4 w = *(const float4*)&w13[ci * COUT + c0];
        float* dst = &sW2[(ci >> 1) * 2 * COUT + (ci & 1)];
        dst[(c0 + 0) * 2] = w.x; dst[(c0 + 1) * 2] = w.y;
        dst[(c0 + 2) * 2] = w.z; dst[(c0 + 3) * 2] = w.w;
    }
    #pragma unroll
    for (int t = 0; t < 7; t++) {
        int e  = tid + t * 256;           // 112 rows x 16 float4
        int r  = e >> 4;
        int q  = e & 15;
        int gr = rbase + r;
        float4 v = (gr < n) ? *(const float4*)&feat[(size_t)gr * CIN + q * 4]
                            : make_float4(0.f, 0.f, 0.f, 0.f);
        *(float4*)&sF[r * CIN + q * 4] = v;
    }
    __syncthreads();

    const int t16 = tid & 15;
    const int r0  = (tid >> 4) * 7;

    ull acc[7][4];
    #pragma unroll
    for (int r = 0; r < 7; r++) {
        acc[r][0] = 0ull; acc[r][1] = 0ull;
        acc[r][2] = 0ull; acc[r][3] = 0ull;
    }

    #pragma unroll 4
    for (int p = 0; p < CIN / 2; p++) {
        ull w0 = *(const ull*)&sW2[p * 128 + (t16     ) * 2];
        ull w1 = *(const ull*)&sW2[p * 128 + (t16 + 16) * 2];
        ull w2 = *(const ull*)&sW2[p * 128 + (t16 + 32) * 2];
        ull w3 = *(const ull*)&sW2[p * 128 + (t16 + 48) * 2];
        #pragma unroll
        for (int r = 0; r < 7; r++) {
            ull f2 = *(const ull*)&sF[(r0 + r) * CIN + p * 2];
            ffma2(acc[r][0], f2, w0);
            ffma2(acc[r][1], f2, w1);
            ffma2(acc[r][2], f2, w2);
            ffma2(acc[r][3], f2, w3);
        }
    }

    #pragma unroll
    for (int r = 0; r < 7; r++) {
        int gr = rbase + r0 + r;
        if (gr < n) {
            float* ob = out + (size_t)gr * COUT + t16;
            ob[0]  = fold(acc[r][0]);
            ob[16] = fold(acc[r][1]);
            ob[32] = fold(acc[r][2]);
            ob[48] = fold(acc[r][3]);
        }
    }
}

// ---------------------------------------------------------------------------
// Tap GEMM: block = 96 rulebook pairs of ONE tap, same f32x2 micro-kernel,
// scatter via atomicAdd. 6 rows x 4 strided cols per thread.
// ---------------------------------------------------------------------------
#define TROWS 96

__global__ void __launch_bounds__(256) tap_gemm_kernel(
    const float* __restrict__ feat, const float* __restrict__ wgt,
    float* __restrict__ out)
{
    const int ky = blockIdx.y;
    int cnt = g_cnt[ky];
    if (cnt > RSLOTS) cnt = RSLOTS;
    const int base = blockIdx.x * TROWS;
    if (base >= cnt) return;

    __shared__ __align__(16) float sW2[CIN * COUT];   // 16 KB
    __shared__ __align__(16) float sF[TROWS * CIN];   // 24 KB
    __shared__ int2 sp[TROWS];

    const int tid = threadIdx.x;

    {
        const float* wk = wgt + (size_t)ky * CIN * COUT;
        #pragma unroll
        for (int t = 0; t < 4; t++) {
            int e  = tid + t * 256;
            int ci = e >> 4;
            int c0 = (e & 15) * 4;
            float4 w = *(const float4*)&wk[ci * COUT + c0];
            float* dst = &sW2[(ci >> 1) * 2 * COUT + (ci & 1)];
            dst[(c0 + 0) * 2] = w.x; dst[(c0 + 1) * 2] = w.y;
            dst[(c0 + 2) * 2] = w.z; dst[(c0 + 3) * 2] = w.w;
        }
    }
    if (tid < TROWS)
        sp[tid] = (base + tid < cnt) ? g_rule[ky][base + tid]
                                     : make_int2(-1, -1);
    __syncthreads();

    #pragma unroll
    for (int t = 0; t < 6; t++) {
        int e = tid + t * 256;       // 96 rows x 16 float4
        int r = e >> 4;
        int q = e & 15;
        int j = sp[r].y;
        float4 v = (j >= 0) ? *(const float4*)&feat[(size_t)j * CIN + q * 4]
                            : make_float4(0.f, 0.f, 0.f, 0.f);
        *(float4*)&sF[r * CIN + q * 4] = v;
    }
    __syncthreads();

    const int t16 = tid & 15;
    const int r0  = (tid >> 4) * 6;

    ull acc[6][4];
    #pragma unroll
    for (int r = 0; r < 6; r++) {
        acc[r][0] = 0ull; acc[r][1] = 0ull;
        acc[r][2] = 0ull; acc[r][3] = 0ull;
    }

    #pragma unroll 4
    for (int p = 0; p < CIN / 2; p++) {
        ull w0 = *(const ull*)&sW2[p * 128 + (t16     ) * 2];
        ull w1 = *(const ull*)&sW2[p * 128 + (t16 + 16) * 2];
        ull w2 = *(const ull*)&sW2[p * 128 + (t16 + 32) * 2];
        ull w3 = *(const ull*)&sW2[p * 128 + (t16 + 48) * 2];
        #pragma unroll
        for (int r = 0; r < 6; r++) {
            ull f2 = *(const ull*)&sF[(r0 + r) * CIN + p * 2];
            ffma2(acc[r][0], f2, w0);
            ffma2(acc[r][1], f2, w1);
            ffma2(acc[r][2], f2, w2);
            ffma2(acc[r][3], f2, w3);
        }
    }

    #pragma unroll
    for (int r = 0; r < 6; r++) {
        int i = sp[r0 + r].x;
        if (i >= 0) {
            float* ob = out + (size_t)i * COUT + t16;
            atomicAdd(ob + 0,  fold(acc[r][0]));
            atomicAdd(ob + 16, fold(acc[r][1]));
            atomicAdd(ob + 32, fold(acc[r][2]));
            atomicAdd(ob + 48, fold(acc[r][3]));
        }
    }
}

// ---------------------------------------------------------------------------
// Merged BN-stats reduce + grid clear (independent work, one launch).
// ---------------------------------------------------------------------------
#define RED_BLOCKS 592

__global__ void __launch_bounds__(256) reduce_clear_kernel(
    const float* __restrict__ out, const int* __restrict__ coords, int n)
{
    if (blockIdx.x >= RED_BLOCKS) {
        int i = (blockIdx.x - RED_BLOCKS) * 256 + threadIdx.x;
        if (i < n) {
            int z = coords[3 * i + 0];
            int y = coords[3 * i + 1];
            int x = coords[3 * i + 2];
            g_grid[(z * HH + y) * WW + x] = 0;
        }
        return;
    }

    const int tid = threadIdx.x;
    const int c4  = (tid & 15) << 2;
    const int rg  = tid >> 4;

    float4 s = make_float4(0.f, 0.f, 0.f, 0.f);
    float4 q = make_float4(0.f, 0.f, 0.f, 0.f);

    for (int row = blockIdx.x * 16 + rg; row < n; row += RED_BLOCKS * 16) {
        float4 v = *(const float4*)&out[(size_t)row * COUT + c4];
        s.x += v.x; s.y += v.y; s.z += v.z; s.w += v.w;
        q.x += v.x * v.x; q.y += v.y * v.y;
        q.z += v.z * v.z; q.w += v.w * v.w;
    }

    s.x += __shfl_xor_sync(0xffffffffu, s.x, 16);
    s.y += __shfl_xor_sync(0xffffffffu, s.y, 16);
    s.z += __shfl_xor_sync(0xffffffffu, s.z, 16);
    s.w += __shfl_xor_sync(0xffffffffu, s.w, 16);
    q.x += __shfl_xor_sync(0xffffffffu, q.x, 16);
    q.y += __shfl_xor_sync(0xffffffffu, q.y, 16);
    q.z += __shfl_xor_sync(0xffffffffu, q.z, 16);
    q.w += __shfl_xor_sync(0xffffffffu, q.w, 16);

    __shared__ float wred[2][8][COUT];
    const int w = tid >> 5;
    if ((tid & 31) < 16) {
        *(float4*)&wred[0][w][c4] = s;
        *(float4*)&wred[1][w][c4] = q;
    }
    __syncthreads();

    if (tid < 2 * COUT) {
        int half = tid >> 6;
        int c    = tid & 63;
        float acc = 0.f;
        #pragma unroll
        for (int ww = 0; ww < 8; ww++) acc += wred[half][ww][c];
        atomicAdd(&g_stats[tid], acc);
    }
}

__global__ void __launch_bounds__(256) bn_kernel(
    float4* __restrict__ out, const float* __restrict__ gamma,
    const float* __restrict__ beta, int n4, float invN)
{
    __shared__ float ssc[COUT], sbi[COUT];
    if (threadIdx.x < COUT) {
        float mean = g_stats[threadIdx.x] * invN;
        float var  = g_stats[COUT + threadIdx.x] * invN - mean * mean;
        float sc   = gamma[threadIdx.x] * rsqrtf(var + EPSV);
        ssc[threadIdx.x] = sc;
        sbi[threadIdx.x] = beta[threadIdx.x] - mean * sc;
    }
    __syncthreads();

    int idx = blockIdx.x * blockDim.x + threadIdx.x;
    if (idx >= n4) return;
    int c4 = (idx & 15) << 2;

    float4 vv = out[idx];
    float r;
    r = vv.x * ssc[c4 + 0] + sbi[c4 + 0]; vv.x = (r >= 0.f) ? r : SLOPE * r;
    r = vv.y * ssc[c4 + 1] + sbi[c4 + 1]; vv.y = (r >= 0.f) ? r : SLOPE * r;
    r = vv.z * ssc[c4 + 2] + sbi[c4 + 2]; vv.z = (r >= 0.f) ? r : SLOPE * r;
    r = vv.w * ssc[c4 + 3] + sbi[c4 + 3]; vv.w = (r >= 0.f) ? r : SLOPE * r;
    out[idx] = vv;
}

extern "C" void kernel_launch(void* const* d_in, const int* in_sizes, int n_in,
                              void* d_out, int out_size)
{
    const float* feat   = (const float*)d_in[0];
    const int*   coords = (const int*)  d_in[1];
    const float* wgt    = (const float*)d_in[2];
    const float* gamma  = (const float*)d_in[3];
    const float* beta   = (const float*)d_in[4];
    float*       out    = (float*)d_out;

    const int n = in_sizes[0] / CIN;

    scatter_kernel<<<(n + 255) / 256, 256>>>(coords, n);
    rulebook_kernel<<<(n * 13 + 255) / 256, 256>>>(coords, n);
    center_gemm_kernel<<<(n + GROWS - 1) / GROWS, 256>>>(feat, wgt, out, n);
    {
        dim3 grid((RSLOTS + TROWS - 1) / TROWS, 27);
        tap_gemm_kernel<<<grid, 256>>>(feat, wgt, out);
    }
    reduce_clear_kernel<<<RED_BLOCKS + (n + 255) / 256, 256>>>(out, coords, n);
    bn_kernel<<<(n * (COUT / 4) + 255) / 256, 256>>>(
        (float4*)out, gamma, beta, n * (COUT / 4), 1.0f / (float)n);
}

// round 8
// speedup vs baseline: 1.9020x; 1.1350x over previous
#include <cuda_runtime.h>
#include <cuda_bf16.h>

typedef unsigned long long ull;
typedef unsigned u32;

#define DD 96
#define HH 320
#define WW 320
#define NVOX (DD*HH*WW)
#define CIN 64
#define COUT 64
#define EPSV 1e-5f
#define SLOPE 0.01f
#define RSLOTS 4096

__device__ int   g_grid[NVOX];          // coord -> row+1, 0 = empty
__device__ float g_stats[2 * COUT];
__device__ int   g_cnt[27];
__device__ int2  g_rule[27][RSLOTS];
// Pre-split, pre-transposed weights: WT[k][co][ci] as bf16 hi/lo (ull = 4 bf16).
__device__ ull   g_wt_hi[27][1024];
__device__ ull   g_wt_lo[27][1024];

// ---------------- helpers ----------------
static __device__ __forceinline__ unsigned pack_bf(float a, float b) {
    __nv_bfloat16 ha = __float2bfloat16(a), hb = __float2bfloat16(b);
    unsigned short ua = *(unsigned short*)&ha, ub = *(unsigned short*)&hb;
    return (unsigned)ua | ((unsigned)ub << 16);
}
static __device__ __forceinline__ void split2(float a, float b,
                                              u32& hi, u32& lo)
{
    __nv_bfloat16 ha = __float2bfloat16(a), hb = __float2bfloat16(b);
    float ra = a - __bfloat162float(ha);
    float rb = b - __bfloat162float(hb);
    hi = pack_bf(a, b);
    lo = pack_bf(ra, rb);
}
static __device__ __forceinline__ void mma16816(
    float* c, u32 a0, u32 a1, u32 a2, u32 a3, u32 b0, u32 b1)
{
    asm volatile(
        "mma.sync.aligned.m16n8k16.row.col.f32.bf16.bf16.f32 "
        "{%0,%1,%2,%3}, {%4,%5,%6,%7}, {%8,%9}, {%0,%1,%2,%3};"
        : "+f"(c[0]), "+f"(c[1]), "+f"(c[2]), "+f"(c[3])
        : "r"(a0), "r"(a1), "r"(a2), "r"(a3), "r"(b0), "r"(b1));
}
// rotation swizzle: u32 column within a 32-u32 row, rotated by 4*row
#define ROT(row, col) (((row) << 5) + (((col) + ((row) << 2)) & 31))

// ---------------- bookkeeping kernels ----------------
__global__ void scatter_kernel(const int* __restrict__ coords, int n) {
    int i = blockIdx.x * blockDim.x + threadIdx.x;
    if (i < 2 * COUT) g_stats[i] = 0.0f;
    if (i < 27) g_cnt[i] = 0;
    if (i >= n) return;
    int z = coords[3 * i + 0];
    int y = coords[3 * i + 1];
    int x = coords[3 * i + 2];
    g_grid[(z * HH + y) * WW + x] = i + 1;
}

__global__ void __launch_bounds__(256) wsplit_kernel(const float* __restrict__ wgt) {
    int idx = blockIdx.x * blockDim.x + threadIdx.x;   // [k][co][ci]
    if (idx >= 27 * 4096) return;
    int k  = idx >> 12;
    int e  = idx & 4095;
    int co = e >> 6;
    int ci = e & 63;
    float w = wgt[(k * 64 + ci) * 64 + co];
    __nv_bfloat16 h = __float2bfloat16(w);
    float r = w - __bfloat162float(h);
    __nv_bfloat16 l = __float2bfloat16(r);
    ((__nv_bfloat16*)g_wt_hi)[idx] = h;
    ((__nv_bfloat16*)g_wt_lo)[idx] = l;
}

__global__ void __launch_bounds__(256) rulebook_kernel(
    const int* __restrict__ coords, int n)
{
    int t = blockIdx.x * blockDim.x + threadIdx.x;
    if (t >= n * 13) return;
    int v = t / 13;
    int k = t - v * 13;

    int z = coords[3 * v + 0] + k / 9       - 1;
    int y = coords[3 * v + 1] + (k / 3) % 3 - 1;
    int x = coords[3 * v + 2] + k % 3       - 1;
    if (z < 0 || z >= DD || y < 0 || y >= HH || x < 0 || x >= WW) return;
    int val = g_grid[(z * HH + y) * WW + x];
    if (val == 0) return;
    int j = val - 1;

    int p0 = atomicAdd(&g_cnt[k], 1);
    if (p0 < RSLOTS) g_rule[k][p0] = make_int2(v, j);
    int p1 = atomicAdd(&g_cnt[26 - k], 1);
    if (p1 < RSLOTS) g_rule[26 - k][p1] = make_int2(j, v);
}

// ---------------------------------------------------------------------------
// MMA core shared by both GEMM kernels. SMEM exactly 48 KB.
// A: 128 rows x 32 u32 (bf16 pairs along ci), rotation-swizzled. hi+lo.
// B: 64 rows (co) x 32 u32 (bf16 pairs along ci), rotation-swizzled. hi+lo.
// 8 warps; warp w owns rows m0=w*16..+15; acc[8][4] f32 per thread.
// 3 passes: Ah*Bh, Al*Bh, Ah*Bl.
// ---------------------------------------------------------------------------
struct MmaSmem {
    u32 Ahi[128 * 32];
    u32 Alo[128 * 32];
    u32 Bhi[64 * 32];
    u32 Blo[64 * 32];
};

static __device__ __forceinline__ void stage_B(
    MmaSmem& s, const ull* __restrict__ wh, const ull* __restrict__ wl, int tid)
{
    #pragma unroll
    for (int t = 0; t < 4; t++) {
        int e  = tid + t * 256;      // 1024 ull entries
        int co = e >> 4;
        int j  = e & 15;             // u32 cols 2j, 2j+1
        ull vh = wh[e];
        ull vl = wl[e];
        s.Bhi[ROT(co, 2 * j    )] = (u32)vh;
        s.Bhi[ROT(co, 2 * j + 1)] = (u32)(vh >> 32);
        s.Blo[ROT(co, 2 * j    )] = (u32)vl;
        s.Blo[ROT(co, 2 * j + 1)] = (u32)(vl >> 32);
    }
}

static __device__ __forceinline__ void mma_passes(
    const MmaSmem& s, float acc[8][4], int m0, int g, int tig)
{
    const int r0 = m0 + g;
    const int r1 = m0 + g + 8;

    #pragma unroll
    for (int pass = 0; pass < 3; pass++) {
        const u32* A = (pass == 1) ? s.Alo : s.Ahi;
        const u32* B = (pass == 2) ? s.Blo : s.Bhi;
        #pragma unroll
        for (int kf = 0; kf < 4; kf++) {
            int ca = kf * 8 + tig;
            u32 a0 = A[ROT(r0, ca)];
            u32 a1 = A[ROT(r1, ca)];
            u32 a2 = A[ROT(r0, ca + 4)];
            u32 a3 = A[ROT(r1, ca + 4)];
            #pragma unroll
            for (int nf = 0; nf < 8; nf++) {
                int rb = nf * 8 + g;
                u32 b0 = B[ROT(rb, ca)];
                u32 b1 = B[ROT(rb, ca + 4)];
                mma16816(acc[nf], a0, a1, a2, a3, b0, b1);
            }
        }
    }
}

// ---------------------------------------------------------------------------
// Center tap: out[128 rows] = feat @ W13.
// ---------------------------------------------------------------------------
__global__ void __launch_bounds__(256) center_mma_kernel(
    const float* __restrict__ feat, float* __restrict__ out, int n)
{
    __shared__ MmaSmem s;
    const int tid   = threadIdx.x;
    const int rbase = blockIdx.x * 128;

    // Stage A hi/lo
    #pragma unroll
    for (int t = 0; t < 8; t++) {
        int e  = tid + t * 256;      // 2048 float4
        int r  = e >> 4;
        int q  = e & 15;
        int gr = rbase + r;
        float4 v = (gr < n) ? *(const float4*)&feat[(size_t)gr * CIN + q * 4]
                            : make_float4(0.f, 0.f, 0.f, 0.f);
        u32 h0, l0, h1, l1;
        split2(v.x, v.y, h0, l0);
        split2(v.z, v.w, h1, l1);
        s.Ahi[ROT(r, 2 * q    )] = h0;
        s.Ahi[ROT(r, 2 * q + 1)] = h1;
        s.Alo[ROT(r, 2 * q    )] = l0;
        s.Alo[ROT(r, 2 * q + 1)] = l1;
    }
    stage_B(s, g_wt_hi[13], g_wt_lo[13], tid);
    __syncthreads();

    const int wid = tid >> 5;
    const int g   = (tid & 31) >> 2;
    const int tig = tid & 3;
    const int m0  = wid * 16;

    float acc[8][4];
    #pragma unroll
    for (int nf = 0; nf < 8; nf++)
        acc[nf][0] = acc[nf][1] = acc[nf][2] = acc[nf][3] = 0.f;

    mma_passes(s, acc, m0, g, tig);

    int row0 = rbase + m0 + g;
    int row1 = row0 + 8;
    #pragma unroll
    for (int nf = 0; nf < 8; nf++) {
        int c = nf * 8 + tig * 2;
        if (row0 < n) *(float2*)&out[(size_t)row0 * COUT + c] =
            make_float2(acc[nf][0], acc[nf][1]);
        if (row1 < n) *(float2*)&out[(size_t)row1 * COUT + c] =
            make_float2(acc[nf][2], acc[nf][3]);
    }
}

// ---------------------------------------------------------------------------
// Tap GEMM: 128 rulebook pairs of ONE tap, atomicAdd scatter.
// ---------------------------------------------------------------------------
__global__ void __launch_bounds__(256) tap_mma_kernel(
    const float* __restrict__ feat, float* __restrict__ out)
{
    const int ky = blockIdx.y;
    int cnt = g_cnt[ky];
    if (cnt > RSLOTS) cnt = RSLOTS;
    const int base = blockIdx.x * 128;
    if (base >= cnt) return;

    __shared__ MmaSmem s;
    const int tid = threadIdx.x;
    const int2* rule = g_rule[ky];

    #pragma unroll
    for (int t = 0; t < 8; t++) {
        int e = tid + t * 256;
        int r = e >> 4;
        int q = e & 15;
        int j = (base + r < cnt) ? rule[base + r].y : -1;
        float4 v = (j >= 0) ? *(const float4*)&feat[(size_t)j * CIN + q * 4]
                            : make_float4(0.f, 0.f, 0.f, 0.f);
        u32 h0, l0, h1, l1;
        split2(v.x, v.y, h0, l0);
        split2(v.z, v.w, h1, l1);
        s.Ahi[ROT(r, 2 * q    )] = h0;
        s.Ahi[ROT(r, 2 * q + 1)] = h1;
        s.Alo[ROT(r, 2 * q    )] = l0;
        s.Alo[ROT(r, 2 * q + 1)] = l1;
    }
    stage_B(s, g_wt_hi[ky], g_wt_lo[ky], tid);
    __syncthreads();

    const int wid = tid >> 5;
    const int g   = (tid & 31) >> 2;
    const int tig = tid & 3;
    const int m0  = wid * 16;

    float acc[8][4];
    #pragma unroll
    for (int nf = 0; nf < 8; nf++)
        acc[nf][0] = acc[nf][1] = acc[nf][2] = acc[nf][3] = 0.f;

    mma_passes(s, acc, m0, g, tig);

    int i0 = (base + m0 + g     < cnt) ? rule[base + m0 + g].x     : -1;
    int i1 = (base + m0 + g + 8 < cnt) ? rule[base + m0 + g + 8].x : -1;
    #pragma unroll
    for (int nf = 0; nf < 8; nf++) {
        int c = nf * 8 + tig * 2;
        if (i0 >= 0) {
            float* ob = out + (size_t)i0 * COUT + c;
            atomicAdd(ob + 0, acc[nf][0]);
            atomicAdd(ob + 1, acc[nf][1]);
        }
        if (i1 >= 0) {
            float* ob = out + (size_t)i1 * COUT + c;
            atomicAdd(ob + 0, acc[nf][2]);
            atomicAdd(ob + 1, acc[nf][3]);
        }
    }
}

// ---------------- BN stats reduce + grid clear (merged) ----------------
#define RED_BLOCKS 592

__global__ void __launch_bounds__(256) reduce_clear_kernel(
    const float* __restrict__ out, const int* __restrict__ coords, int n)
{
    if (blockIdx.x >= RED_BLOCKS) {
        int i = (blockIdx.x - RED_BLOCKS) * 256 + threadIdx.x;
        if (i < n) {
            int z = coords[3 * i + 0];
            int y = coords[3 * i + 1];
            int x = coords[3 * i + 2];
            g_grid[(z * HH + y) * WW + x] = 0;
        }
        return;
    }

    const int tid = threadIdx.x;
    const int c4  = (tid & 15) << 2;
    const int rg  = tid >> 4;

    float4 sv = make_float4(0.f, 0.f, 0.f, 0.f);
    float4 qv = make_float4(0.f, 0.f, 0.f, 0.f);

    for (int row = blockIdx.x * 16 + rg; row < n; row += RED_BLOCKS * 16) {
        float4 v = *(const float4*)&out[(size_t)row * COUT + c4];
        sv.x += v.x; sv.y += v.y; sv.z += v.z; sv.w += v.w;
        qv.x += v.x * v.x; qv.y += v.y * v.y;
        qv.z += v.z * v.z; qv.w += v.w * v.w;
    }

    sv.x += __shfl_xor_sync(0xffffffffu, sv.x, 16);
    sv.y += __shfl_xor_sync(0xffffffffu, sv.y, 16);
    sv.z += __shfl_xor_sync(0xffffffffu, sv.z, 16);
    sv.w += __shfl_xor_sync(0xffffffffu, sv.w, 16);
    qv.x += __shfl_xor_sync(0xffffffffu, qv.x, 16);
    qv.y += __shfl_xor_sync(0xffffffffu, qv.y, 16);
    qv.z += __shfl_xor_sync(0xffffffffu, qv.z, 16);
    qv.w += __shfl_xor_sync(0xffffffffu, qv.w, 16);

    __shared__ float wred[2][8][COUT];
    const int w = tid >> 5;
    if ((tid & 31) < 16) {
        *(float4*)&wred[0][w][c4] = sv;
        *(float4*)&wred[1][w][c4] = qv;
    }
    __syncthreads();

    if (tid < 2 * COUT) {
        int half = tid >> 6;
        int c    = tid & 63;
        float acc = 0.f;
        #pragma unroll
        for (int ww = 0; ww < 8; ww++) acc += wred[half][ww][c];
        atomicAdd(&g_stats[tid], acc);
    }
}

__global__ void __launch_bounds__(256) bn_kernel(
    float4* __restrict__ out, const float* __restrict__ gamma,
    const float* __restrict__ beta, int n4, float invN)
{
    __shared__ float ssc[COUT], sbi[COUT];
    if (threadIdx.x < COUT) {
        float mean = g_stats[threadIdx.x] * invN;
        float var  = g_stats[COUT + threadIdx.x] * invN - mean * mean;
        float sc   = gamma[threadIdx.x] * rsqrtf(var + EPSV);
        ssc[threadIdx.x] = sc;
        sbi[threadIdx.x] = beta[threadIdx.x] - mean * sc;
    }
    __syncthreads();

    int idx = blockIdx.x * blockDim.x + threadIdx.x;
    if (idx >= n4) return;
    int c4 = (idx & 15) << 2;

    float4 vv = out[idx];
    float r;
    r = vv.x * ssc[c4 + 0] + sbi[c4 + 0]; vv.x = (r >= 0.f) ? r : SLOPE * r;
    r = vv.y * ssc[c4 + 1] + sbi[c4 + 1]; vv.y = (r >= 0.f) ? r : SLOPE * r;
    r = vv.z * ssc[c4 + 2] + sbi[c4 + 2]; vv.z = (r >= 0.f) ? r : SLOPE * r;
    r = vv.w * ssc[c4 + 3] + sbi[c4 + 3]; vv.w = (r >= 0.f) ? r : SLOPE * r;
    out[idx] = vv;
}

extern "C" void kernel_launch(void* const* d_in, const int* in_sizes, int n_in,
                              void* d_out, int out_size)
{
    const float* feat   = (const float*)d_in[0];
    const int*   coords = (const int*)  d_in[1];
    const float* wgt    = (const float*)d_in[2];
    const float* gamma  = (const float*)d_in[3];
    const float* beta   = (const float*)d_in[4];
    float*       out    = (float*)d_out;

    const int n = in_sizes[0] / CIN;

    scatter_kernel<<<(n + 255) / 256, 256>>>(coords, n);
    wsplit_kernel<<<(27 * 4096 + 255) / 256, 256>>>(wgt);
    rulebook_kernel<<<(n * 13 + 255) / 256, 256>>>(coords, n);
    center_mma_kernel<<<(n + 127) / 128, 256>>>(feat, out, n);
    {
        dim3 grid(RSLOTS / 128, 27);
        tap_mma_kernel<<<grid, 256>>>(feat, out);
    }
    reduce_clear_kernel<<<RED_BLOCKS + (n + 255) / 256, 256>>>(out, coords, n);
    bn_kernel<<<(n * (COUT / 4) + 255) / 256, 256>>>(
        (float4*)out, gamma, beta, n * (COUT / 4), 1.0f / (float)n);
}